// round 13
// baseline (speedup 1.0000x reference)
#include <cuda_runtime.h>
#include <math.h>

#define T_LEN 32768
#define I_DIM 128
#define H_DIM 512
#define G_DIM 2048
#define NHEAD 25
#define NCTA 64
#define POISON 0x7FBFFFFFu       // quiet NaN; |h|<1 so real h bits never equal this
#define WDOG   (1u << 28)        // ~268M poll iters ≈ >>100s: unreachable when healthy

// Device-global scratch (no allocation allowed anywhere).
__device__ float    g_xg[T_LEN * G_DIM];            // permuted pre-activations (268 MB)
__device__ float    g_part[T_LEN * NCTA];           // per-step per-CTA head partials (8 MB)
__device__ float    g_v[H_DIM];                     // fused head vector v = W1^T Wout^T
__device__ float    g_c0;                           // fused head constant b1 . Wout
// Full-length h sequence: slot t holds h(t); written exactly once per launch.
// Data IS the notification: word != POISON <=> value is final. No tags, no ring.
__device__ __align__(128) unsigned int g_hseq[(T_LEN + 1) * H_DIM];   // 67 MB

// f32x2 packed FMA (sm_100+): d = a*b + c on two packed floats.
__device__ __forceinline__ unsigned long long fma2(unsigned long long a,
                                                   unsigned long long b,
                                                   unsigned long long c) {
    unsigned long long d;
    asm("fma.rn.f32x2 %0, %1, %2, %3;" : "=l"(d) : "l"(a), "l"(b), "l"(c));
    return d;
}

__device__ __forceinline__ float fsigmoid(float x) {
    return __fdividef(1.f, 1.f + __expf(-x));
}
__device__ __forceinline__ float ftanh_fast(float x) {
    // 1 - 2/(e^{2x}+1); saturates cleanly at +-1 for large |x|.
    return 1.f - 2.f * __fdividef(1.f, __expf(2.f * x) + 1.f);
}

// ---------------------------------------------------------------------------
// Kernel 0a: poison the whole h sequence; row 0 = h(0) = 0 (graph-replay safe:
// every replay fully re-initializes).
// ---------------------------------------------------------------------------
__global__ __launch_bounds__(256) void poison_kernel() {
    const int total = (T_LEN + 1) * H_DIM;
    int stride = gridDim.x * blockDim.x;
    for (int i = blockIdx.x * blockDim.x + threadIdx.x; i < total; i += stride)
        g_hseq[i] = (i < H_DIM) ? 0u : POISON;
}

// ---------------------------------------------------------------------------
// Kernel 0b: fuse head weights.
// ---------------------------------------------------------------------------
__global__ void prep_kernel(const float* __restrict__ W1,
                            const float* __restrict__ b1,
                            const float* __restrict__ Wout) {
    int tid = threadIdx.x;
    if (tid < H_DIM) {
        float s = 0.f;
        for (int k = 0; k < NHEAD; k++) s += Wout[k] * W1[k * H_DIM + tid];
        g_v[tid] = s;
    }
    if (tid == 0) {
        float s = 0.f;
        for (int k = 0; k < NHEAD; k++) s += b1[k] * Wout[k];
        g_c0 = s;
    }
}

// ---------------------------------------------------------------------------
// Kernel 1: xg[t, colp] = x[t] . W_ih[grow] + (b_ih+b_hh)[grow], permuted so
// warp u of the LSTM kernel reads one float4 (i,f,g,o for its unit):
//   colp = u*4 + gate,  grow = gate*512 + u.
// ---------------------------------------------------------------------------
__global__ __launch_bounds__(256) void xg_kernel(const float* __restrict__ x,
                                                 const float* __restrict__ W_ih,
                                                 const float* __restrict__ b_ih,
                                                 const float* __restrict__ b_hh) {
    __shared__ float Xs[32][I_DIM];
    int tb    = blockIdx.x;       // 0..1023 (32 timesteps each)
    int cb    = blockIdx.y;       // 0..7    (256 columns each)
    int tid   = threadIdx.x;
    int tbase = tb * 32;

    for (int idx = tid; idx < 32 * I_DIM; idx += 256)
        Xs[idx >> 7][idx & 127] = x[(tbase + (idx >> 7)) * I_DIM + (idx & 127)];
    __syncthreads();

    int col  = cb * 256 + tid;            // permuted column
    int u    = col >> 2;
    int gate = col & 3;
    int grow = gate * 512 + u;
    float bias = b_ih[grow] + b_hh[grow];

    float acc[32];
#pragma unroll
    for (int tt = 0; tt < 32; tt++) acc[tt] = bias;

    const float4* Wr = (const float4*)(W_ih + grow * I_DIM);
    for (int kq = 0; kq < 32; kq++) {
        float4 w4 = Wr[kq];
#pragma unroll
        for (int tt = 0; tt < 32; tt++) {
            float4 x4 = *(const float4*)&Xs[tt][kq * 4];
            acc[tt] += w4.x * x4.x + w4.y * x4.y + w4.z * x4.z + w4.w * x4.w;
        }
    }
#pragma unroll
    for (int tt = 0; tt < 32; tt++)
        g_xg[(tbase + tt) * G_DIM + col] = acc[tt];
}

// ---------------------------------------------------------------------------
// Kernel 2: persistent sequential LSTM. 64 CTAs x 256 threads.
// Warp w of CTA cb owns unit u = cb*8+w (gate rows u, 512+u, 1024+u, 1536+u),
// W_hh slice register-resident. Per step: each thread polls the two 4B words
// it owns of g_hseq[t] (one 8B relaxed load) until both != POISON, stages h
// into smem; matvec (packed f32x2) + shfl reduce; lane0 runs the LSTM cell
// and publishes h(t+1) with ONE st.relaxed.gpu.b32. No tags, no ring reuse,
// no fences: each word is written once and is its own ready flag.
// WATCHDOG: every poll loop is iteration-bounded. A healthy detect takes
// <100 iters; the bound (~268M) only trips if the pipeline is wedged, in
// which case the CTA abandons deterministically (clean wrong-answer failure
// instead of an un-killable device hang).
// ---------------------------------------------------------------------------
__global__ __launch_bounds__(256, 1) void lstm_kernel(const float* __restrict__ W_hh) {
    __shared__ float hbuf[H_DIM];
    __shared__ float pbuf[8];
    __shared__ int   dead;
    int tid = threadIdx.x;
    int w   = tid >> 5;
    int l   = tid & 31;
    int cb  = blockIdx.x;
    int u   = cb * 8 + w;

    if (tid == 0) dead = 0;

    // Register-resident W_hh: row r (gate) covers h[4l+128m .. +4).
    float4 wr[4][4];
#pragma unroll
    for (int r = 0; r < 4; r++) {
        const float* row = W_hh + (r * 512 + u) * H_DIM;
#pragma unroll
        for (int m = 0; m < 4; m++)
            wr[r][m] = *(const float4*)(row + 4 * l + 128 * m);
    }

    float cstate = 0.f;
    float vval   = (l == 0) ? g_v[u] : 0.f;

    float4 xg4 = make_float4(0.f, 0.f, 0.f, 0.f);
    if (l == 0) xg4 = *(const float4*)&g_xg[0 * G_DIM + u * 4];   // prefetch t=0
    __syncthreads();

    for (int t = 0; t < T_LEN; t++) {
        // Prefetch next step's gate pre-activations (DRAM latency hidden).
        float4 xg_next = make_float4(0.f, 0.f, 0.f, 0.f);
        if (l == 0 && t + 1 < T_LEN)
            xg_next = *(const float4*)&g_xg[(t + 1) * G_DIM + u * 4];

        // Poll the two h words this thread owns (one scalar 8B relaxed load;
        // each aligned 4B half is independently poison-or-final).
        {
            const unsigned int* p0 = &g_hseq[t * H_DIM + 2 * tid];
            unsigned long long v;
            unsigned int spins = 0;
            do {
                asm volatile("ld.relaxed.gpu.global.b64 %0, [%1];"
                             : "=l"(v) : "l"(p0) : "memory");
                if (++spins >= WDOG) { dead = 1; break; }   // watchdog
            } while (((unsigned)v == POISON) ||
                     ((unsigned)(v >> 32) == POISON));
            hbuf[2 * tid]     = __uint_as_float((unsigned)v);
            hbuf[2 * tid + 1] = __uint_as_float((unsigned)(v >> 32));
        }
        __syncthreads();
        if (dead) break;   // uniform across CTA (smem flag read after barrier)

        // Matvec: 4 gate rows x 16 h-elems per lane, packed f32x2.
        unsigned long long acc2[4] = {0ull, 0ull, 0ull, 0ull};
#pragma unroll
        for (int m = 0; m < 4; m++) {
            float4 h4 = *(const float4*)&hbuf[4 * l + 128 * m];   // conflict-free
            unsigned long long hlo = *(const unsigned long long*)&h4.x;
            unsigned long long hhi = *(const unsigned long long*)&h4.z;
#pragma unroll
            for (int r = 0; r < 4; r++) {
                unsigned long long wlo = *(const unsigned long long*)&wr[r][m].x;
                unsigned long long whi = *(const unsigned long long*)&wr[r][m].z;
                acc2[r] = fma2(wlo, hlo, acc2[r]);
                acc2[r] = fma2(whi, hhi, acc2[r]);
            }
        }
        float acc[4];
#pragma unroll
        for (int r = 0; r < 4; r++) {
            unsigned int lo = (unsigned int)acc2[r];
            unsigned int hi = (unsigned int)(acc2[r] >> 32);
            acc[r] = __uint_as_float(lo) + __uint_as_float(hi);
        }
#pragma unroll
        for (int off = 16; off > 0; off >>= 1) {
#pragma unroll
            for (int r = 0; r < 4; r++)
                acc[r] += __shfl_xor_sync(0xffffffffu, acc[r], off);
        }

        // Lane 0 of each warp: LSTM cell + single 4B publish of h(t+1).
        if (l == 0) {
            float iv = fsigmoid(acc[0] + xg4.x);
            float fv = fsigmoid(acc[1] + xg4.y);
            float gv = ftanh_fast(acc[2] + xg4.z);
            float ov = fsigmoid(acc[3] + xg4.w);
            cstate = fv * cstate + iv * gv;
            float hv = ov * ftanh_fast(cstate);
            asm volatile("st.relaxed.gpu.global.b32 [%0], %1;"
                         :: "l"(&g_hseq[(t + 1) * H_DIM + u]),
                            "r"(__float_as_uint(hv))
                         : "memory");
            pbuf[w] = hv * vval;
        }
        xg4 = xg_next;
        __syncthreads();   // hbuf reads done; pbuf complete

        if (tid == 0) {    // off critical path: per-CTA head partial
            float s = pbuf[0] + pbuf[1] + pbuf[2] + pbuf[3]
                    + pbuf[4] + pbuf[5] + pbuf[6] + pbuf[7];
            g_part[t * NCTA + cb] = s;
        }
    }
}

// ---------------------------------------------------------------------------
// Kernel 3: out[t] = c0 + sum_cb g_part[t][cb]
// ---------------------------------------------------------------------------
__global__ void head_kernel(float* __restrict__ out) {
    int t = blockIdx.x * blockDim.x + threadIdx.x;
    if (t >= T_LEN) return;
    float s = g_c0;
    const float4* p = (const float4*)&g_part[t * NCTA];
#pragma unroll
    for (int q = 0; q < NCTA / 4; q++) {
        float4 v = p[q];
        s += v.x + v.y + v.z + v.w;
    }
    out[t] = s;
}

// ---------------------------------------------------------------------------
extern "C" void kernel_launch(void* const* d_in, const int* in_sizes, int n_in,
                              void* d_out, int out_size) {
    const float* x    = (const float*)d_in[0];
    const float* W_ih = (const float*)d_in[1];
    const float* W_hh = (const float*)d_in[2];
    const float* b_ih = (const float*)d_in[3];
    const float* b_hh = (const float*)d_in[4];
    const float* W1   = (const float*)d_in[5];
    const float* b1   = (const float*)d_in[6];
    const float* Wout = (const float*)d_in[7];
    float* out = (float*)d_out;

    (void)in_sizes; (void)n_in; (void)out_size;

    poison_kernel<<<512, 256>>>();
    prep_kernel<<<1, 512>>>(W1, b1, Wout);
    dim3 gx(T_LEN / 32, G_DIM / 256);
    xg_kernel<<<gx, 256>>>(x, W_ih, b_ih, b_hh);
    lstm_kernel<<<NCTA, 256>>>(W_hh);
    head_kernel<<<T_LEN / 256, 256>>>(out);
}